// round 5
// baseline (speedup 1.0000x reference)
#include <cuda_runtime.h>
#include <math.h>

// Problem constants
#define BB   512          // batch
#define TT   256          // time steps
#define HH   50           // hidden
#define GG   200          // 4*H gates
#define II   144          // input features
#define MM   (BB*TT)      // 131072 rows for the projection GEMMs
#define OO   144          // fc output

// Scratch (static __device__ globals — no allocations anywhere).
// Kernels reference these directly; kernel_launch makes NO runtime API calls
// other than kernel launches (maximally graph-capture-safe).
__device__ float g_xproj[(size_t)MM * GG];   // ~105 MB, reused by both layers
__device__ float g_h1[(size_t)MM * HH];      // ~26 MB, layer-0 hidden sequence
__device__ float g_hlast[BB * HH];           // layer-1 final hidden

// ---------------------------------------------------------------------------
// GEMM: g_xproj[m][n] = sum_k A[m][k] * W[n][k] + b1[n] + b2[n]
// SRC=0: A = param pointer (the model input, K=144)
// SRC=1: A = g_h1 (layer-0 hidden sequence, K=50)
// Tile 64x64xBK16, 256 threads, 4x4 microtile, float4 shared reads.
// ---------------------------------------------------------------------------
template <int SRC>
__global__ __launch_bounds__(256) void gemm_xw(
    const float* __restrict__ Ain, const float* __restrict__ W,
    const float* __restrict__ b1, const float* __restrict__ b2, int K)
{
    const float* __restrict__ A = (SRC == 0) ? Ain : (const float*)g_h1;

    const int BK = 16;
    __shared__ float As[16][68];   // [k][m]; row stride 68 floats = 272B (16B-aligned)
    __shared__ float Bs[16][68];   // [k][n]

    const int tid = threadIdx.x;
    const int tx  = tid & 15;       // n direction (4 cols each)
    const int ty  = tid >> 4;       // m direction (4 rows each)
    const int m0  = blockIdx.x * 64;
    const int n0  = blockIdx.y * 64;

    float acc[4][4] = {};

    const int ktiles = (K + BK - 1) / BK;
    for (int kt = 0; kt < ktiles; ++kt) {
        const int k0 = kt * BK;
        // Load A tile: 64 rows x 16 k (1024 elems, 4 per thread)
        #pragma unroll
        for (int l = 0; l < 4; ++l) {
            int idx = tid + l * 256;
            int r = idx >> 4, kk = idx & 15;
            int k = k0 + kk;
            As[kk][r] = (k < K) ? A[(size_t)(m0 + r) * K + k] : 0.f;
        }
        // Load W tile: 64 gates x 16 k
        #pragma unroll
        for (int l = 0; l < 4; ++l) {
            int idx = tid + l * 256;
            int n = idx >> 4, kk = idx & 15;
            int k = k0 + kk;
            int gn = n0 + n;
            Bs[kk][n] = (k < K && gn < GG) ? W[(size_t)gn * K + k] : 0.f;
        }
        __syncthreads();
        #pragma unroll
        for (int kk = 0; kk < BK; ++kk) {
            float4 av = *(const float4*)&As[kk][ty * 4];
            float4 bv = *(const float4*)&Bs[kk][tx * 4];
            float a[4] = {av.x, av.y, av.z, av.w};
            float b[4] = {bv.x, bv.y, bv.z, bv.w};
            #pragma unroll
            for (int i = 0; i < 4; ++i)
                #pragma unroll
                for (int j = 0; j < 4; ++j)
                    acc[i][j] = fmaf(a[i], b[j], acc[i][j]);
        }
        __syncthreads();
    }

    // Epilogue: add combined bias, store float4 (GG % 4 == 0 so all-or-nothing)
    const int nbase = n0 + tx * 4;
    if (nbase < GG) {
        float bias[4];
        #pragma unroll
        for (int j = 0; j < 4; ++j) bias[j] = b1[nbase + j] + b2[nbase + j];
        #pragma unroll
        for (int i = 0; i < 4; ++i) {
            int m = m0 + ty * 4 + i;
            float4 v;
            v.x = acc[i][0] + bias[0];
            v.y = acc[i][1] + bias[1];
            v.z = acc[i][2] + bias[2];
            v.w = acc[i][3] + bias[3];
            *(float4*)&g_xproj[(size_t)m * GG + nbase] = v;
        }
    }
}

// ---------------------------------------------------------------------------
// LSTM recurrence for one layer. Reads pre-activations from g_xproj.
// One block per batch element. Threads 0..199 = gate threads; each holds its
// w_hh row (50 floats, zero-padded to 52) in registers. h lives in shared as
// 13 float4 (broadcast reads). Threads 0..49 do the cell update.
// WRITE_ALL=1: write h for every t into g_h1 (layer 0).
// WRITE_ALL=0: write only t=T-1 into g_hlast (layer 1).
// ---------------------------------------------------------------------------
template <int WRITE_ALL>
__global__ __launch_bounds__(256) void lstm_rec(
    const float* __restrict__ w_hh)  // [G, H]
{
    __shared__ float4 h4[13];        // 52 floats; [50],[51] stay 0 forever
    __shared__ float  gsh[GG];       // activated gates
    float* hsh = (float*)h4;

    const int tid = threadIdx.x;
    const int b   = blockIdx.x;

    float wreg[52];
    if (tid < GG) {
        #pragma unroll
        for (int k = 0; k < HH; ++k) wreg[k] = __ldg(&w_hh[tid * HH + k]);
        wreg[50] = 0.f; wreg[51] = 0.f;
    }
    if (tid < 52) hsh[tid] = 0.f;
    float c = 0.f;
    __syncthreads();

    const float* xpb = g_xproj + (size_t)b * TT * GG;

    for (int t = 0; t < TT; ++t) {
        if (tid < GG) {
            // issue x-proj load early; consumed only after the dot product
            float xv = __ldg(&xpb[t * GG + tid]);
            float a0 = 0.f, a1 = 0.f, a2 = 0.f, a3 = 0.f;
            #pragma unroll
            for (int kk = 0; kk < 13; ++kk) {
                float4 hv = h4[kk];
                a0 = fmaf(wreg[kk * 4 + 0], hv.x, a0);
                a1 = fmaf(wreg[kk * 4 + 1], hv.y, a1);
                a2 = fmaf(wreg[kk * 4 + 2], hv.z, a2);
                a3 = fmaf(wreg[kk * 4 + 3], hv.w, a3);
            }
            float pre = xv + ((a0 + a1) + (a2 + a3));
            // gate sections: 0:i(sig) 1:f(sig) 2:g(tanh) 3:o(sig)
            int sect = tid / HH;
            float v = (sect == 2) ? tanhf(pre) : (1.f / (1.f + expf(-pre)));
            gsh[tid] = v;
        }
        __syncthreads();   // gates ready; everyone done reading h
        if (tid < HH) {
            float iv = gsh[tid];
            float fv = gsh[HH + tid];
            float gv = gsh[2 * HH + tid];
            float ov = gsh[3 * HH + tid];
            c = fmaf(fv, c, iv * gv);
            float h = ov * tanhf(c);
            hsh[tid] = h;
            if (WRITE_ALL) {
                g_h1[((size_t)b * TT + t) * HH + tid] = h;
            } else if (t == TT - 1) {
                g_hlast[(size_t)b * HH + tid] = h;
            }
        }
        __syncthreads();   // h ready for next step
    }
}

// ---------------------------------------------------------------------------
// Final FC: out[b][o] = sum_k g_hlast[b][k] * w_fc[o][k] + b_fc[o]
// ---------------------------------------------------------------------------
__global__ __launch_bounds__(OO) void fc_kernel(
    const float* __restrict__ w_fc, const float* __restrict__ b_fc,
    float* __restrict__ out)
{
    __shared__ float hs[HH];
    const int b = blockIdx.x;
    const int o = threadIdx.x;
    if (o < HH) hs[o] = g_hlast[b * HH + o];
    __syncthreads();
    float acc = b_fc[o];
    #pragma unroll
    for (int k = 0; k < HH; ++k) acc = fmaf(__ldg(&w_fc[o * HH + k]), hs[k], acc);
    out[(size_t)b * OO + o] = acc;
}

// ---------------------------------------------------------------------------
extern "C" void kernel_launch(void* const* d_in, const int* in_sizes, int n_in,
                              void* d_out, int out_size)
{
    (void)in_sizes; (void)n_in; (void)out_size;
    const float* x     = (const float*)d_in[0];
    const float* w_ih0 = (const float*)d_in[1];
    const float* w_hh0 = (const float*)d_in[2];
    const float* b_ih0 = (const float*)d_in[3];
    const float* b_hh0 = (const float*)d_in[4];
    const float* w_ih1 = (const float*)d_in[5];
    const float* w_hh1 = (const float*)d_in[6];
    const float* b_ih1 = (const float*)d_in[7];
    const float* b_hh1 = (const float*)d_in[8];
    const float* w_fc  = (const float*)d_in[9];
    const float* b_fc  = (const float*)d_in[10];
    float* out = (float*)d_out;

    dim3 gemmGrid(MM / 64, (GG + 63) / 64);   // 2048 x 4

    // Layer 0 input projection: g_xproj = x @ w_ih0^T + b_ih0 + b_hh0
    gemm_xw<0><<<gemmGrid, 256>>>(x, w_ih0, b_ih0, b_hh0, II);
    // Layer 0 recurrence -> g_h1 (full sequence)
    lstm_rec<1><<<BB, 256>>>(w_hh0);
    // Layer 1 input projection: g_xproj = g_h1 @ w_ih1^T + b_ih1 + b_hh1
    gemm_xw<1><<<gemmGrid, 256>>>(nullptr, w_ih1, b_ih1, b_hh1, HH);
    // Layer 1 recurrence -> g_hlast (last hidden only)
    lstm_rec<0><<<BB, 256>>>(w_hh1);
    // FC head
    fc_kernel<<<BB, OO>>>(w_fc, b_fc, out);
}

// round 6
// speedup vs baseline: 1.4062x; 1.4062x over previous
#include <cuda_runtime.h>
#include <math.h>

// Problem constants
#define BB   512          // batch
#define TT   256          // time steps
#define HH   50           // hidden
#define GG   200          // 4*H gates
#define II   144          // input features
#define MM   (BB*TT)      // 131072 rows for the projection GEMMs
#define OO   144          // fc output

// Scratch (static __device__ globals — no allocations anywhere).
__device__ float g_xproj[(size_t)MM * GG];   // ~105 MB, reused by both layers
__device__ float g_h1[(size_t)MM * HH];      // ~26 MB, layer-0 hidden sequence
__device__ float g_hlast[BB * HH];           // layer-1 final hidden

// Fast activations via the MUFU.TANH hardware unit (sm_75+).
__device__ __forceinline__ float fast_tanh(float x) {
    float y;
    asm("tanh.approx.f32 %0, %1;" : "=f"(y) : "f"(x));
    return y;
}
__device__ __forceinline__ float fast_sigmoid(float x) {
    return fmaf(0.5f, fast_tanh(0.5f * x), 0.5f);
}

// ---------------------------------------------------------------------------
// GEMM: g_xproj[m][n] = sum_k A[m][k] * W[n][k] + b1[n] + b2[n]
// SRC=0: A = param pointer (model input, K=144); SRC=1: A = g_h1 (K=50)
// Tile 64x64xBK16, 256 threads, 4x4 microtile, float4 shared reads.
// Measured ~80% of fp32 FFMA roofline — unchanged this round.
// ---------------------------------------------------------------------------
template <int SRC>
__global__ __launch_bounds__(256) void gemm_xw(
    const float* __restrict__ Ain, const float* __restrict__ W,
    const float* __restrict__ b1, const float* __restrict__ b2, int K)
{
    const float* __restrict__ A = (SRC == 0) ? Ain : (const float*)g_h1;

    const int BK = 16;
    __shared__ float As[16][68];
    __shared__ float Bs[16][68];

    const int tid = threadIdx.x;
    const int tx  = tid & 15;       // n direction (4 cols each)
    const int ty  = tid >> 4;       // m direction (4 rows each)
    const int m0  = blockIdx.x * 64;
    const int n0  = blockIdx.y * 64;

    float acc[4][4] = {};

    const int ktiles = (K + BK - 1) / BK;
    for (int kt = 0; kt < ktiles; ++kt) {
        const int k0 = kt * BK;
        #pragma unroll
        for (int l = 0; l < 4; ++l) {
            int idx = tid + l * 256;
            int r = idx >> 4, kk = idx & 15;
            int k = k0 + kk;
            As[kk][r] = (k < K) ? A[(size_t)(m0 + r) * K + k] : 0.f;
        }
        #pragma unroll
        for (int l = 0; l < 4; ++l) {
            int idx = tid + l * 256;
            int n = idx >> 4, kk = idx & 15;
            int k = k0 + kk;
            int gn = n0 + n;
            Bs[kk][n] = (k < K && gn < GG) ? W[(size_t)gn * K + k] : 0.f;
        }
        __syncthreads();
        #pragma unroll
        for (int kk = 0; kk < BK; ++kk) {
            float4 av = *(const float4*)&As[kk][ty * 4];
            float4 bv = *(const float4*)&Bs[kk][tx * 4];
            float a[4] = {av.x, av.y, av.z, av.w};
            float b[4] = {bv.x, bv.y, bv.z, bv.w};
            #pragma unroll
            for (int i = 0; i < 4; ++i)
                #pragma unroll
                for (int j = 0; j < 4; ++j)
                    acc[i][j] = fmaf(a[i], b[j], acc[i][j]);
        }
        __syncthreads();
    }

    const int nbase = n0 + tx * 4;
    if (nbase < GG) {
        float bias[4];
        #pragma unroll
        for (int j = 0; j < 4; ++j) bias[j] = b1[nbase + j] + b2[nbase + j];
        #pragma unroll
        for (int i = 0; i < 4; ++i) {
            int m = m0 + ty * 4 + i;
            float4 v;
            v.x = acc[i][0] + bias[0];
            v.y = acc[i][1] + bias[1];
            v.z = acc[i][2] + bias[2];
            v.w = acc[i][3] + bias[3];
            *(float4*)&g_xproj[(size_t)m * GG + nbase] = v;
        }
    }
}

// ---------------------------------------------------------------------------
// LSTM recurrence, v2.
//   - 2 batch elements per block (threads 0..199 -> batch 2*blk, 200..399 ->
//     batch 2*blk+1, 400..415 idle-but-uniform). Grid=256, 2 blocks/SM ->
//     single wave.
//   - Unit-major mapping: thread 4u+g holds w_hh row (g*50+u) in registers.
//     All 4 gates of unit u sit in 4 adjacent lanes -> cell update via
//     __shfl_down_sync, no gate staging in smem.
//   - h double-buffered in shared -> exactly ONE __syncthreads per step.
//   - Distance-2 prefetch of the x-projection stream.
//   - tanh.approx.f32 activations.
// WRITE_ALL=1: write h for every t into g_h1.  WRITE_ALL=0: last h -> g_hlast.
// ---------------------------------------------------------------------------
template <int WRITE_ALL>
__global__ __launch_bounds__(416, 2) void lstm_rec2(
    const float* __restrict__ w_hh)  // [G, H]
{
    __shared__ float hbuf[2][2][64];   // [buf][bat][unit], pad slots stay 0

    const int tid = threadIdx.x;
    const int bat = (tid >= 200) ? 1 : 0;
    const int j   = tid - bat * 200;   // 0..215
    const int u   = j >> 2;            // 0..53
    const int gt  = j & 3;             // 0:i 1:f 2:g 3:o
    const bool real = (u < HH);
    const int b   = blockIdx.x * 2 + bat;
    const int wrow = gt * HH + u;      // valid iff real

    // Per-thread w_hh row in registers (padded to 52 for float4 h reads)
    float w[52];
    if (real) {
        #pragma unroll
        for (int k = 0; k < HH; ++k) w[k] = __ldg(&w_hh[wrow * HH + k]);
    } else {
        #pragma unroll
        for (int k = 0; k < HH; ++k) w[k] = 0.f;
    }
    w[50] = 0.f; w[51] = 0.f;

    // Zero both h buffers (256 floats)
    if (tid < 256) ((float*)hbuf)[tid] = 0.f;

    float c = 0.f;

    // x-projection stream for this (batch, gate-row); distance-2 prefetch
    const float* xpb = g_xproj + (size_t)b * TT * GG + (real ? wrow : 0);
    float xv0 = real ? __ldg(xpb + 0 * GG) : 0.f;
    float xv1 = real ? __ldg(xpb + 1 * GG) : 0.f;

    __syncthreads();

    for (int t = 0; t < TT; ++t) {
        const int buf = t & 1;

        // prefetch step t+2
        float xvn = 0.f;
        if (real && t + 2 < TT) xvn = __ldg(xpb + (size_t)(t + 2) * GG);

        // gate pre-activation: w . h  (h broadcast from shared, float4)
        const float4* h4 = (const float4*)hbuf[buf][bat];
        float a0 = 0.f, a1 = 0.f, a2 = 0.f, a3 = 0.f;
        #pragma unroll
        for (int kk = 0; kk < 13; ++kk) {
            float4 hv = h4[kk];
            a0 = fmaf(w[kk * 4 + 0], hv.x, a0);
            a1 = fmaf(w[kk * 4 + 1], hv.y, a1);
            a2 = fmaf(w[kk * 4 + 2], hv.z, a2);
            a3 = fmaf(w[kk * 4 + 3], hv.w, a3);
        }
        float pre = xv0 + ((a0 + a1) + (a2 + a3));
        float v = (gt == 2) ? fast_tanh(pre) : fast_sigmoid(pre);

        // gather f, g, o into the i-lane (groups of 4 lanes, warp-aligned)
        float fv = __shfl_down_sync(0xffffffffu, v, 1);
        float gv = __shfl_down_sync(0xffffffffu, v, 2);
        float ov = __shfl_down_sync(0xffffffffu, v, 3);

        if (gt == 0) {
            c = fmaf(fv, c, v * gv);           // v == i here
            float h = ov * fast_tanh(c);
            hbuf[buf ^ 1][bat][u] = h;         // idle leaders write 0 to pad
            if (WRITE_ALL) {
                if (real) g_h1[((size_t)b * TT + t) * HH + u] = h;
            } else {
                if (real && t == TT - 1) g_hlast[(size_t)b * HH + u] = h;
            }
        }

        xv0 = xv1; xv1 = xvn;
        __syncthreads();   // h(t) visible for step t+1; single barrier/step
    }
}

// ---------------------------------------------------------------------------
// Final FC: out[b][o] = sum_k g_hlast[b][k] * w_fc[o][k] + b_fc[o]
// ---------------------------------------------------------------------------
__global__ __launch_bounds__(OO) void fc_kernel(
    const float* __restrict__ w_fc, const float* __restrict__ b_fc,
    float* __restrict__ out)
{
    __shared__ float hs[HH];
    const int b = blockIdx.x;
    const int o = threadIdx.x;
    if (o < HH) hs[o] = g_hlast[b * HH + o];
    __syncthreads();
    float acc = b_fc[o];
    #pragma unroll
    for (int k = 0; k < HH; ++k) acc = fmaf(__ldg(&w_fc[o * HH + k]), hs[k], acc);
    out[(size_t)b * OO + o] = acc;
}

// ---------------------------------------------------------------------------
extern "C" void kernel_launch(void* const* d_in, const int* in_sizes, int n_in,
                              void* d_out, int out_size)
{
    (void)in_sizes; (void)n_in; (void)out_size;
    const float* x     = (const float*)d_in[0];
    const float* w_ih0 = (const float*)d_in[1];
    const float* w_hh0 = (const float*)d_in[2];
    const float* b_ih0 = (const float*)d_in[3];
    const float* b_hh0 = (const float*)d_in[4];
    const float* w_ih1 = (const float*)d_in[5];
    const float* w_hh1 = (const float*)d_in[6];
    const float* b_ih1 = (const float*)d_in[7];
    const float* b_hh1 = (const float*)d_in[8];
    const float* w_fc  = (const float*)d_in[9];
    const float* b_fc  = (const float*)d_in[10];
    float* out = (float*)d_out;

    dim3 gemmGrid(MM / 64, (GG + 63) / 64);   // 2048 x 4

    gemm_xw<0><<<gemmGrid, 256>>>(x, w_ih0, b_ih0, b_hh0, II);
    lstm_rec2<1><<<BB / 2, 416>>>(w_hh0);
    gemm_xw<1><<<gemmGrid, 256>>>(nullptr, w_ih1, b_ih1, b_hh1, HH);
    lstm_rec2<0><<<BB / 2, 416>>>(w_hh1);
    fc_kernel<<<BB, OO>>>(w_fc, b_fc, out);
}

// round 10
// speedup vs baseline: 1.5124x; 1.0755x over previous
#include <cuda_runtime.h>
#include <math.h>

// Problem constants
#define BB   512          // batch
#define TT   256          // time steps
#define HH   50           // hidden
#define GG   200          // 4*H gates
#define II   144          // input features
#define MM   (BB*TT)      // 131072 rows for the projection GEMMs
#define OO   144          // fc output

// Scratch (static __device__ globals — no allocations anywhere).
__device__ float g_xproj[(size_t)MM * GG];   // ~105 MB, reused by both layers
__device__ float g_h1[(size_t)MM * HH];      // ~26 MB, layer-0 hidden sequence
__device__ float g_hlast[BB * HH];           // layer-1 final hidden

// ---------------------------------------------------------------------------
// Small PTX helpers
// ---------------------------------------------------------------------------
__device__ __forceinline__ float fast_tanh(float x) {
    float y; asm("tanh.approx.f32 %0, %1;" : "=f"(y) : "f"(x)); return y;
}
__device__ __forceinline__ float fast_sigmoid(float x) {
    return fmaf(0.5f, fast_tanh(0.5f * x), 0.5f);
}
__device__ __forceinline__ unsigned f2tf32(float x) {
    unsigned u; asm("cvt.rna.tf32.f32 %0, %1;" : "=r"(u) : "f"(x)); return u;
}
__device__ __forceinline__ unsigned long long pk2(float lo, float hi) {
    unsigned long long r; asm("mov.b64 %0, {%1, %2};" : "=l"(r) : "f"(lo), "f"(hi)); return r;
}
__device__ __forceinline__ float2 upk2(unsigned long long v) {
    float2 f; asm("mov.b64 {%0, %1}, %2;" : "=f"(f.x), "=f"(f.y) : "l"(v)); return f;
}
__device__ __forceinline__ unsigned long long fma2(
    unsigned long long a, unsigned long long b, unsigned long long c) {
    unsigned long long d;
    asm("fma.rn.f32x2 %0, %1, %2, %3;" : "=l"(d) : "l"(a), "l"(b), "l"(c));
    return d;
}
// m16n8k8 tf32 MMA, acc in fp32
__device__ __forceinline__ void mma_tf32(float* c, const unsigned* a, const unsigned* b) {
    asm volatile(
        "mma.sync.aligned.m16n8k8.row.col.f32.tf32.tf32.f32 "
        "{%0,%1,%2,%3}, {%4,%5,%6,%7}, {%8,%9}, {%0,%1,%2,%3};\n"
        : "+f"(c[0]), "+f"(c[1]), "+f"(c[2]), "+f"(c[3])
        : "r"(a[0]), "r"(a[1]), "r"(a[2]), "r"(a[3]), "r"(b[0]), "r"(b[1]));
}

// ---------------------------------------------------------------------------
// Tensor-core projection GEMM (3xTF32 for fp32-class accuracy):
//   g_xproj[m][n] = sum_k A[m][k]*W[n][k] + b1[n] + b2[n]
// Block tile: 128(M) x 40(N), 256 threads = 8 warps, warp = 16 rows x 40 cols
// (1 m-frag x 5 n-frags). Stage BK=16 through shared (hi+lo tf32), 2 syncs
// per stage, next stage's global loads prefetched before compute.
// K=144 (SRC=0, vector loads) or K=50 (SRC=1, A=g_h1, scalar guarded loads).
// N tiled 5x40 = 200 exactly — zero N padding waste.
// ---------------------------------------------------------------------------
template <int K, int KT, int SRC>
__global__ __launch_bounds__(256) void gemm_tc(
    const float* __restrict__ Ain, const float* __restrict__ W,
    const float* __restrict__ b1, const float* __restrict__ b2)
{
    const float* __restrict__ A = (SRC == 0) ? Ain : (const float*)g_h1;

    __shared__ unsigned AsH[128][18], AsL[128][18];
    __shared__ unsigned BsH[40][18],  BsL[40][18];

    const int tid  = threadIdx.x;
    const int lane = tid & 31;
    const int warp = tid >> 5;
    const int wm   = warp * 16;          // warp's m offset in the tile
    const int g    = lane >> 2;          // 0..7
    const int tg   = lane & 3;           // 0..3
    const int m0   = blockIdx.x * 128;
    const int n0   = blockIdx.y * 40;

    // global-load assignment
    const int arow = tid >> 1;           // 0..127
    const int akq  = tid & 1;            // which 8-wide k half
    const int brow = tid >> 2;           // 0..63 (valid < 40)
    const int bkj  = tid & 3;            // which 4-wide k quarter

    float acc[5][4];
    #pragma unroll
    for (int nf = 0; nf < 5; ++nf)
        #pragma unroll
        for (int i = 0; i < 4; ++i) acc[nf][i] = 0.f;

    float va[8];
    float vb[4];

    // ---- load stage 0 into regs ----
    {
        const int k0 = 0;
        if (K % 8 == 0) {
            float4 p0 = *(const float4*)&A[(size_t)(m0 + arow) * K + k0 + akq * 8];
            float4 p1 = *(const float4*)&A[(size_t)(m0 + arow) * K + k0 + akq * 8 + 4];
            va[0]=p0.x; va[1]=p0.y; va[2]=p0.z; va[3]=p0.w;
            va[4]=p1.x; va[5]=p1.y; va[6]=p1.z; va[7]=p1.w;
        } else {
            #pragma unroll
            for (int j = 0; j < 8; ++j) {
                int k = k0 + akq * 8 + j;
                va[j] = (k < K) ? A[(size_t)(m0 + arow) * K + k] : 0.f;
            }
        }
        if (brow < 40) {
            if (K % 4 == 0) {
                float4 p = *(const float4*)&W[(size_t)(n0 + brow) * K + k0 + bkj * 4];
                vb[0]=p.x; vb[1]=p.y; vb[2]=p.z; vb[3]=p.w;
            } else {
                #pragma unroll
                for (int j = 0; j < 4; ++j) {
                    int k = k0 + bkj * 4 + j;
                    vb[j] = (k < K) ? W[(size_t)(n0 + brow) * K + k] : 0.f;
                }
            }
        }
    }

    for (int kt = 0; kt < KT; ++kt) {
        __syncthreads();           // previous stage's compute done
        // ---- convert + store stage kt to shared ----
        #pragma unroll
        for (int j = 0; j < 8; ++j) {
            float x = va[j];
            unsigned h = f2tf32(x);
            AsH[arow][akq * 8 + j] = h;
            AsL[arow][akq * 8 + j] = f2tf32(x - __uint_as_float(h));
        }
        if (brow < 40) {
            #pragma unroll
            for (int j = 0; j < 4; ++j) {
                float x = vb[j];
                unsigned h = f2tf32(x);
                BsH[brow][bkj * 4 + j] = h;
                BsL[brow][bkj * 4 + j] = f2tf32(x - __uint_as_float(h));
            }
        }
        __syncthreads();           // stage visible

        // ---- prefetch stage kt+1 (global latency overlapped with MMA) ----
        if (kt + 1 < KT) {
            const int k0 = (kt + 1) * 16;
            if (K % 8 == 0) {
                float4 p0 = *(const float4*)&A[(size_t)(m0 + arow) * K + k0 + akq * 8];
                float4 p1 = *(const float4*)&A[(size_t)(m0 + arow) * K + k0 + akq * 8 + 4];
                va[0]=p0.x; va[1]=p0.y; va[2]=p0.z; va[3]=p0.w;
                va[4]=p1.x; va[5]=p1.y; va[6]=p1.z; va[7]=p1.w;
            } else {
                #pragma unroll
                for (int j = 0; j < 8; ++j) {
                    int k = k0 + akq * 8 + j;
                    va[j] = (k < K) ? A[(size_t)(m0 + arow) * K + k] : 0.f;
                }
            }
            if (brow < 40) {
                #pragma unroll
                for (int j = 0; j < 4; ++j) {
                    int k = k0 + bkj * 4 + j;
                    vb[j] = (k < K) ? W[(size_t)(n0 + brow) * K + k] : 0.f;
                }
            }
        }

        // ---- compute: 2 k-frags x 5 n-frags x 3 MMAs (3xTF32) ----
        #pragma unroll
        for (int k8 = 0; k8 < 2; ++k8) {
            const int kb = k8 * 8;
            unsigned aH[4], aL[4];
            aH[0] = AsH[wm + g][kb + tg];      aH[1] = AsH[wm + g + 8][kb + tg];
            aH[2] = AsH[wm + g][kb + tg + 4];  aH[3] = AsH[wm + g + 8][kb + tg + 4];
            aL[0] = AsL[wm + g][kb + tg];      aL[1] = AsL[wm + g + 8][kb + tg];
            aL[2] = AsL[wm + g][kb + tg + 4];  aL[3] = AsL[wm + g + 8][kb + tg + 4];
            #pragma unroll
            for (int nf = 0; nf < 5; ++nf) {
                unsigned bH[2], bL[2];
                bH[0] = BsH[nf * 8 + g][kb + tg]; bH[1] = BsH[nf * 8 + g][kb + tg + 4];
                bL[0] = BsL[nf * 8 + g][kb + tg]; bL[1] = BsL[nf * 8 + g][kb + tg + 4];
                mma_tf32(acc[nf], aH, bH);
                mma_tf32(acc[nf], aH, bL);
                mma_tf32(acc[nf], aL, bH);
            }
        }
    }

    // ---- epilogue: bias + store (all cols valid: 5x40 = 200 exact) ----
    const int m_lo = m0 + wm + g;
    const int m_hi = m_lo + 8;
    #pragma unroll
    for (int nf = 0; nf < 5; ++nf) {
        const int n = n0 + nf * 8 + 2 * tg;
        float bs0 = __ldg(&b1[n])     + __ldg(&b2[n]);
        float bs1 = __ldg(&b1[n + 1]) + __ldg(&b2[n + 1]);
        float2 v0 = make_float2(acc[nf][0] + bs0, acc[nf][1] + bs1);
        float2 v1 = make_float2(acc[nf][2] + bs0, acc[nf][3] + bs1);
        *(float2*)&g_xproj[(size_t)m_lo * GG + n] = v0;
        *(float2*)&g_xproj[(size_t)m_hi * GG + n] = v1;
    }
}

// ---------------------------------------------------------------------------
// LSTM recurrence v3.
//   - 2 independent batch halves per block (224 threads each, 448 total),
//     synced with NAMED barriers (bar.sync 1/2, 224) so the halves never
//     stall each other. Grid=256, 2 blocks/SM -> one wave.
//   - thread 4u+gt holds w_hh row (gt*50+u) as 26 packed f32x2 operands;
//     inner product = 13 x { ld.shared.v2.u64 ; 2 x fma.rn.f32x2 } — half
//     the FMA issue count of the scalar version.
//   - gates of one unit sit in 4 adjacent lanes -> cell update via shfl.
//   - h double-buffered in shared; ONE barrier per step.
// ---------------------------------------------------------------------------
template <int WRITE_ALL>
__global__ __launch_bounds__(448, 2) void lstm_rec3(
    const float* __restrict__ w_hh)  // [G, H]
{
    __shared__ float hbuf[2][2][64];   // [buf][bat][unit]; pads stay harmless

    const int tid = threadIdx.x;
    const int bat = (tid >= 224) ? 1 : 0;
    const int j   = tid - bat * 224;   // 0..223
    const int u   = j >> 2;            // 0..55
    const int gt  = j & 3;             // 0:i 1:f 2:g 3:o
    const bool real = (u < HH);
    const int b    = blockIdx.x * 2 + bat;
    const int wrow = gt * HH + u;

    // packed w_hh row: 25 real pairs + 1 zero pair (covers h pad slots 50,51)
    unsigned long long w2[26];
    if (real) {
        #pragma unroll
        for (int k = 0; k < 25; ++k)
            w2[k] = pk2(__ldg(&w_hh[wrow * HH + 2 * k]),
                        __ldg(&w_hh[wrow * HH + 2 * k + 1]));
    } else {
        #pragma unroll
        for (int k = 0; k < 25; ++k) w2[k] = 0ull;
    }
    w2[25] = 0ull;

    if (j < 128) hbuf[j >> 6][bat][j & 63] = 0.f;

    float c = 0.f;
    const float* xpb = g_xproj + (size_t)b * TT * GG + (real ? wrow : 0);
    float xv0 = real ? __ldg(xpb) : 0.f;
    float xv1 = real ? __ldg(xpb + GG) : 0.f;

    asm volatile("bar.sync %0, %1;" :: "r"(bat + 1), "r"(224) : "memory");

    for (int t = 0; t < TT; ++t) {
        const int buf = t & 1;
        float xvn = (real && t + 2 < TT) ? __ldg(xpb + (size_t)(t + 2) * GG) : 0.f;

        const ulonglong2* h2 = (const ulonglong2*)hbuf[buf][bat];
        unsigned long long acc0 = 0ull, acc1 = 0ull;   // (+0,+0) packed
        #pragma unroll
        for (int kk = 0; kk < 13; ++kk) {
            ulonglong2 hv = h2[kk];
            acc0 = fma2(w2[2 * kk],     hv.x, acc0);
            acc1 = fma2(w2[2 * kk + 1], hv.y, acc1);
        }
        float2 f0 = upk2(acc0), f1 = upk2(acc1);
        float pre = xv0 + ((f0.x + f0.y) + (f1.x + f1.y));
        float v = (gt == 2) ? fast_tanh(pre) : fast_sigmoid(pre);

        float fv = __shfl_down_sync(0xffffffffu, v, 1);
        float gv = __shfl_down_sync(0xffffffffu, v, 2);
        float ov = __shfl_down_sync(0xffffffffu, v, 3);

        if (gt == 0) {
            c = fmaf(fv, c, v * gv);                  // v == i gate here
            float h = ov * fast_tanh(c);
            hbuf[buf ^ 1][bat][u] = real ? h : 0.f;   // pads stay 0
            if (WRITE_ALL) {
                if (real) g_h1[((size_t)b * TT + t) * HH + u] = h;
            } else {
                if (real && t == TT - 1) g_hlast[(size_t)b * HH + u] = h;
            }
        }

        xv0 = xv1; xv1 = xvn;
        asm volatile("bar.sync %0, %1;" :: "r"(bat + 1), "r"(224) : "memory");
    }
}

// ---------------------------------------------------------------------------
// Final FC: out[b][o] = sum_k g_hlast[b][k] * w_fc[o][k] + b_fc[o]
// ---------------------------------------------------------------------------
__global__ __launch_bounds__(OO) void fc_kernel(
    const float* __restrict__ w_fc, const float* __restrict__ b_fc,
    float* __restrict__ out)
{
    __shared__ float hs[HH];
    const int b = blockIdx.x;
    const int o = threadIdx.x;
    if (o < HH) hs[o] = g_hlast[b * HH + o];
    __syncthreads();
    float acc = b_fc[o];
    #pragma unroll
    for (int k = 0; k < HH; ++k) acc = fmaf(__ldg(&w_fc[o * HH + k]), hs[k], acc);
    out[(size_t)b * OO + o] = acc;
}

// ---------------------------------------------------------------------------
extern "C" void kernel_launch(void* const* d_in, const int* in_sizes, int n_in,
                              void* d_out, int out_size)
{
    (void)in_sizes; (void)n_in; (void)out_size;
    const float* x     = (const float*)d_in[0];
    const float* w_ih0 = (const float*)d_in[1];
    const float* w_hh0 = (const float*)d_in[2];
    const float* b_ih0 = (const float*)d_in[3];
    const float* b_hh0 = (const float*)d_in[4];
    const float* w_ih1 = (const float*)d_in[5];
    const float* w_hh1 = (const float*)d_in[6];
    const float* b_ih1 = (const float*)d_in[7];
    const float* b_hh1 = (const float*)d_in[8];
    const float* w_fc  = (const float*)d_in[9];
    const float* b_fc  = (const float*)d_in[10];
    float* out = (float*)d_out;

    dim3 gemmGrid(MM / 128, 5);   // 1024 x 5, N covered exactly

    gemm_tc<II, 9, 0><<<gemmGrid, 256>>>(x, w_ih0, b_ih0, b_hh0);
    lstm_rec3<1><<<BB / 2, 448>>>(w_hh0);
    gemm_tc<HH, 4, 1><<<gemmGrid, 256>>>(nullptr, w_ih1, b_ih1, b_hh1);
    lstm_rec3<0><<<BB / 2, 448>>>(w_hh1);
    fc_kernel<<<BB, OO>>>(w_fc, b_fc, out);
}

// round 14
// speedup vs baseline: 1.7079x; 1.1293x over previous
#include <cuda_runtime.h>
#include <cuda_fp16.h>
#include <math.h>

// Problem constants
#define BB   512          // batch
#define TT   256          // time steps
#define HH   50           // hidden
#define GG   200          // 4*H gates
#define II   144          // input features
#define MM   (BB*TT)      // 131072 rows for the projection GEMMs
#define OO   144          // fc output

// Scratch (static __device__ globals — no allocations anywhere).
__device__ float g_xproj[(size_t)MM * GG];   // ~105 MB, reused by both layers
__device__ float g_h1[(size_t)MM * HH];      // ~26 MB, layer-0 hidden sequence
__device__ float g_hlast[BB * HH];           // layer-1 final hidden

// ---------------------------------------------------------------------------
// Small helpers
// ---------------------------------------------------------------------------
__device__ __forceinline__ float fast_tanh(float x) {
    float y; asm("tanh.approx.f32 %0, %1;" : "=f"(y) : "f"(x)); return y;
}
__device__ __forceinline__ float fast_sigmoid(float x) {
    return fmaf(0.5f, fast_tanh(0.5f * x), 0.5f);
}
__device__ __forceinline__ unsigned long long pk2(float lo, float hi) {
    unsigned long long r; asm("mov.b64 %0, {%1, %2};" : "=l"(r) : "f"(lo), "f"(hi)); return r;
}
__device__ __forceinline__ float2 upk2(unsigned long long v) {
    float2 f; asm("mov.b64 {%0, %1}, %2;" : "=f"(f.x), "=f"(f.y) : "l"(v)); return f;
}
__device__ __forceinline__ unsigned long long fma2(
    unsigned long long a, unsigned long long b, unsigned long long c) {
    unsigned long long d;
    asm("fma.rn.f32x2 %0, %1, %2, %3;" : "=l"(d) : "l"(a), "l"(b), "l"(c));
    return d;
}
// Split (x0,x1) into hi/lo f16x2 words using standard intrinsics.
// Register layout: low 16 bits = x0 (even k), high 16 bits = x1 (odd k) —
// exactly the layout mma.m16n8k16 expects for a k-pair.
__device__ __forceinline__ void split16(float x0, float x1, unsigned& h, unsigned& l) {
    __half2 hh = __floats2half2_rn(x0, x1);
    float2  hf = __half22float2(hh);
    __half2 ll = __floats2half2_rn(x0 - hf.x, x1 - hf.y);
    h = *reinterpret_cast<unsigned*>(&hh);
    l = *reinterpret_cast<unsigned*>(&ll);
}
// m16n8k16 f16 MMA, fp32 accumulate
__device__ __forceinline__ void mma_f16(float* c, const unsigned* a, const unsigned* b) {
    asm volatile(
        "mma.sync.aligned.m16n8k16.row.col.f32.f16.f16.f32 "
        "{%0,%1,%2,%3}, {%4,%5,%6,%7}, {%8,%9}, {%0,%1,%2,%3};\n"
        : "+f"(c[0]), "+f"(c[1]), "+f"(c[2]), "+f"(c[3])
        : "r"(a[0]), "r"(a[1]), "r"(a[2]), "r"(a[3]), "r"(b[0]), "r"(b[1]));
}

// ---------------------------------------------------------------------------
// Tensor-core projection GEMM, split-FP16 (3 MMA terms: hi*hi + hi*lo + lo*hi
// -> ~22 mantissa bits, fp32-class):
//   g_xproj[m][n] = sum_k A[m][k]*W[n][k] + b1[n] + b2[n]
// Block tile 128(M) x 40(N), 256 threads = 8 warps, warp = 16 rows x 40 cols.
// Stage BK=16 through shared as packed f16x2 k-pairs; one m16n8k16 covers the
// whole stage -> 15 MMAs + 28 LDS per warp-stage (half of the tf32 version).
// ---------------------------------------------------------------------------
template <int K, int KT, int SRC>
__global__ __launch_bounds__(256) void gemm_f16(
    const float* __restrict__ Ain, const float* __restrict__ W,
    const float* __restrict__ b1, const float* __restrict__ b2)
{
    const float* __restrict__ A = (SRC == 0) ? Ain : (const float*)g_h1;

    // k-pairs: 8 per row used, row stride 12 u32 (48B) -> conflict-spread frags
    __shared__ unsigned AsH[128][12], AsL[128][12];
    __shared__ unsigned BsH[40][12],  BsL[40][12];

    const int tid  = threadIdx.x;
    const int lane = tid & 31;
    const int warp = tid >> 5;
    const int wm   = warp * 16;          // warp's m offset in the tile
    const int g    = lane >> 2;          // 0..7
    const int tg   = lane & 3;           // 0..3
    const int m0   = blockIdx.x * 128;
    const int n0   = blockIdx.y * 40;

    // global-load assignment
    const int arow = tid >> 1;           // 0..127
    const int akq  = tid & 1;            // which 8-wide k half
    const int brow = tid >> 2;           // 0..63 (valid < 40)
    const int bkj  = tid & 3;            // which 4-wide k quarter

    float acc[5][4];
    #pragma unroll
    for (int nf = 0; nf < 5; ++nf)
        #pragma unroll
        for (int i = 0; i < 4; ++i) acc[nf][i] = 0.f;

    float va[8];
    float vb[4];

    // ---- load stage 0 into regs ----
    {
        #pragma unroll
        for (int j = 0; j < 8; ++j) {
            int k = akq * 8 + j;
            va[j] = (k < K) ? A[(size_t)(m0 + arow) * K + k] : 0.f;
        }
        if (brow < 40) {
            #pragma unroll
            for (int j = 0; j < 4; ++j) {
                int k = bkj * 4 + j;
                vb[j] = (k < K) ? W[(size_t)(n0 + brow) * K + k] : 0.f;
            }
        }
    }

    for (int kt = 0; kt < KT; ++kt) {
        __syncthreads();           // previous stage's compute done
        // ---- split-convert + store stage kt to shared (plain 32-bit STS) ----
        #pragma unroll
        for (int p = 0; p < 4; ++p) {
            unsigned h, l;
            split16(va[2 * p], va[2 * p + 1], h, l);
            AsH[arow][akq * 4 + p] = h;
            AsL[arow][akq * 4 + p] = l;
        }
        if (brow < 40) {
            #pragma unroll
            for (int p = 0; p < 2; ++p) {
                unsigned h, l;
                split16(vb[2 * p], vb[2 * p + 1], h, l);
                BsH[brow][bkj * 2 + p] = h;
                BsL[brow][bkj * 2 + p] = l;
            }
        }
        __syncthreads();           // stage visible

        // ---- prefetch stage kt+1 (global latency overlapped with MMA) ----
        if (kt + 1 < KT) {
            const int k0 = (kt + 1) * 16;
            #pragma unroll
            for (int j = 0; j < 8; ++j) {
                int k = k0 + akq * 8 + j;
                va[j] = (k < K) ? A[(size_t)(m0 + arow) * K + k] : 0.f;
            }
            if (brow < 40) {
                #pragma unroll
                for (int j = 0; j < 4; ++j) {
                    int k = k0 + bkj * 4 + j;
                    vb[j] = (k < K) ? W[(size_t)(n0 + brow) * K + k] : 0.f;
                }
            }
        }

        // ---- compute: one k16 frag x 5 n-frags x 3 MMAs (split-fp16) ----
        {
            unsigned aH[4], aL[4];
            aH[0] = AsH[wm + g][tg];      aH[1] = AsH[wm + g + 8][tg];
            aH[2] = AsH[wm + g][tg + 4];  aH[3] = AsH[wm + g + 8][tg + 4];
            aL[0] = AsL[wm + g][tg];      aL[1] = AsL[wm + g + 8][tg];
            aL[2] = AsL[wm + g][tg + 4];  aL[3] = AsL[wm + g + 8][tg + 4];
            #pragma unroll
            for (int nf = 0; nf < 5; ++nf) {
                unsigned bH[2], bL[2];
                bH[0] = BsH[nf * 8 + g][tg]; bH[1] = BsH[nf * 8 + g][tg + 4];
                bL[0] = BsL[nf * 8 + g][tg]; bL[1] = BsL[nf * 8 + g][tg + 4];
                mma_f16(acc[nf], aH, bH);
                mma_f16(acc[nf], aH, bL);
                mma_f16(acc[nf], aL, bH);
            }
        }
    }

    // ---- epilogue: bias + store (5x40 = 200 exact, no N guard) ----
    const int m_lo = m0 + wm + g;
    const int m_hi = m_lo + 8;
    #pragma unroll
    for (int nf = 0; nf < 5; ++nf) {
        const int n = n0 + nf * 8 + 2 * tg;
        float bs0 = __ldg(&b1[n])     + __ldg(&b2[n]);
        float bs1 = __ldg(&b1[n + 1]) + __ldg(&b2[n + 1]);
        g_xproj[(size_t)m_lo * GG + n]     = acc[nf][0] + bs0;
        g_xproj[(size_t)m_lo * GG + n + 1] = acc[nf][1] + bs1;
        g_xproj[(size_t)m_hi * GG + n]     = acc[nf][2] + bs0;
        g_xproj[(size_t)m_hi * GG + n + 1] = acc[nf][3] + bs1;
    }
}

// ---------------------------------------------------------------------------
// LSTM recurrence v3 (byte-identical to the R10 kernel that passed at
// 160us/layer, issue-bound).
// ---------------------------------------------------------------------------
template <int WRITE_ALL>
__global__ __launch_bounds__(448, 2) void lstm_rec3(
    const float* __restrict__ w_hh)  // [G, H]
{
    __shared__ float hbuf[2][2][64];   // [buf][bat][unit]; pads stay harmless

    const int tid = threadIdx.x;
    const int bat = (tid >= 224) ? 1 : 0;
    const int j   = tid - bat * 224;   // 0..223
    const int u   = j >> 2;            // 0..55
    const int gt  = j & 3;             // 0:i 1:f 2:g 3:o
    const bool real = (u < HH);
    const int b    = blockIdx.x * 2 + bat;
    const int wrow = gt * HH + u;

    // packed w_hh row: 25 real pairs + 1 zero pair (covers h pad slots 50,51)
    unsigned long long w2[26];
    if (real) {
        #pragma unroll
        for (int k = 0; k < 25; ++k)
            w2[k] = pk2(__ldg(&w_hh[wrow * HH + 2 * k]),
                        __ldg(&w_hh[wrow * HH + 2 * k + 1]));
    } else {
        #pragma unroll
        for (int k = 0; k < 25; ++k) w2[k] = 0ull;
    }
    w2[25] = 0ull;

    if (j < 128) hbuf[j >> 6][bat][j & 63] = 0.f;

    float c = 0.f;
    const float* xpb = g_xproj + (size_t)b * TT * GG + (real ? wrow : 0);
    float xv0 = real ? __ldg(xpb) : 0.f;
    float xv1 = real ? __ldg(xpb + GG) : 0.f;

    asm volatile("bar.sync %0, %1;" :: "r"(bat + 1), "r"(224) : "memory");

    for (int t = 0; t < TT; ++t) {
        const int buf = t & 1;
        float xvn = (real && t + 2 < TT) ? __ldg(xpb + (size_t)(t + 2) * GG) : 0.f;

        const ulonglong2* h2 = (const ulonglong2*)hbuf[buf][bat];
        unsigned long long acc0 = 0ull, acc1 = 0ull;   // (+0,+0) packed
        #pragma unroll
        for (int kk = 0; kk < 13; ++kk) {
            ulonglong2 hv = h2[kk];
            acc0 = fma2(w2[2 * kk],     hv.x, acc0);
            acc1 = fma2(w2[2 * kk + 1], hv.y, acc1);
        }
        float2 f0 = upk2(acc0), f1 = upk2(acc1);
        float pre = xv0 + ((f0.x + f0.y) + (f1.x + f1.y));
        float v = (gt == 2) ? fast_tanh(pre) : fast_sigmoid(pre);

        float fv = __shfl_down_sync(0xffffffffu, v, 1);
        float gv = __shfl_down_sync(0xffffffffu, v, 2);
        float ov = __shfl_down_sync(0xffffffffu, v, 3);

        if (gt == 0) {
            c = fmaf(fv, c, v * gv);                  // v == i gate here
            float h = ov * fast_tanh(c);
            hbuf[buf ^ 1][bat][u] = real ? h : 0.f;   // pads stay 0
            if (WRITE_ALL) {
                if (real) g_h1[((size_t)b * TT + t) * HH + u] = h;
            } else {
                if (real && t == TT - 1) g_hlast[(size_t)b * HH + u] = h;
            }
        }

        xv0 = xv1; xv1 = xvn;
        asm volatile("bar.sync %0, %1;" :: "r"(bat + 1), "r"(224) : "memory");
    }
}

// ---------------------------------------------------------------------------
// Final FC: out[b][o] = sum_k g_hlast[b][k] * w_fc[o][k] + b_fc[o]
// ---------------------------------------------------------------------------
__global__ __launch_bounds__(OO) void fc_kernel(
    const float* __restrict__ w_fc, const float* __restrict__ b_fc,
    float* __restrict__ out)
{
    __shared__ float hs[HH];
    const int b = blockIdx.x;
    const int o = threadIdx.x;
    if (o < HH) hs[o] = g_hlast[b * HH + o];
    __syncthreads();
    float acc = b_fc[o];
    #pragma unroll
    for (int k = 0; k < HH; ++k) acc = fmaf(__ldg(&w_fc[o * HH + k]), hs[k], acc);
    out[(size_t)b * OO + o] = acc;
}

// ---------------------------------------------------------------------------
extern "C" void kernel_launch(void* const* d_in, const int* in_sizes, int n_in,
                              void* d_out, int out_size)
{
    (void)in_sizes; (void)n_in; (void)out_size;
    const float* x     = (const float*)d_in[0];
    const float* w_ih0 = (const float*)d_in[1];
    const float* w_hh0 = (const float*)d_in[2];
    const float* b_ih0 = (const float*)d_in[3];
    const float* b_hh0 = (const float*)d_in[4];
    const float* w_ih1 = (const float*)d_in[5];
    const float* w_hh1 = (const float*)d_in[6];
    const float* b_ih1 = (const float*)d_in[7];
    const float* b_hh1 = (const float*)d_in[8];
    const float* w_fc  = (const float*)d_in[9];
    const float* b_fc  = (const float*)d_in[10];
    float* out = (float*)d_out;

    dim3 gemmGrid(MM / 128, 5);   // 1024 x 5, N covered exactly

    gemm_f16<II, 9, 0><<<gemmGrid, 256>>>(x, w_ih0, b_ih0, b_hh0);
    lstm_rec3<1><<<BB / 2, 448>>>(w_hh0);
    gemm_f16<HH, 4, 1><<<gemmGrid, 256>>>(nullptr, w_ih1, b_ih1, b_hh1);
    lstm_rec3<0><<<BB / 2, 448>>>(w_hh1);
    fc_kernel<<<BB, OO>>>(w_fc, b_fc, out);
}

// round 15
// speedup vs baseline: 1.7499x; 1.0246x over previous
#include <cuda_runtime.h>
#include <cuda_fp16.h>
#include <math.h>

// Problem constants
#define BB   512          // batch
#define TT   256          // time steps
#define HH   50           // hidden
#define GG   200          // 4*H gates
#define II   144          // input features
#define MM   (BB*TT)      // 131072 rows for the projection GEMMs
#define OO   144          // fc output

// Scratch (static __device__ globals — no allocations anywhere).
__device__ float g_xproj[(size_t)MM * GG];   // ~105 MB, reused by both layers
__device__ float g_h1[(size_t)MM * HH];      // ~26 MB, layer-0 hidden sequence
__device__ float g_hlast[BB * HH];           // layer-1 final hidden

// ---------------------------------------------------------------------------
// Small helpers
// ---------------------------------------------------------------------------
__device__ __forceinline__ float fast_tanh(float x) {
    float y; asm("tanh.approx.f32 %0, %1;" : "=f"(y) : "f"(x)); return y;
}
__device__ __forceinline__ float fast_sigmoid(float x) {
    return fmaf(0.5f, fast_tanh(0.5f * x), 0.5f);
}
__device__ __forceinline__ unsigned long long pk2(float lo, float hi) {
    unsigned long long r; asm("mov.b64 %0, {%1, %2};" : "=l"(r) : "f"(lo), "f"(hi)); return r;
}
__device__ __forceinline__ float2 upk2(unsigned long long v) {
    float2 f; asm("mov.b64 {%0, %1}, %2;" : "=f"(f.x), "=f"(f.y) : "l"(v)); return f;
}
__device__ __forceinline__ unsigned long long fma2(
    unsigned long long a, unsigned long long b, unsigned long long c) {
    unsigned long long d;
    asm("fma.rn.f32x2 %0, %1, %2, %3;" : "=l"(d) : "l"(a), "l"(b), "l"(c));
    return d;
}
// Split (x0,x1) into hi/lo f16x2 words (low 16 bits = x0 / even k).
__device__ __forceinline__ void split16(float x0, float x1, unsigned& h, unsigned& l) {
    __half2 hh = __floats2half2_rn(x0, x1);
    float2  hf = __half22float2(hh);
    __half2 ll = __floats2half2_rn(x0 - hf.x, x1 - hf.y);
    h = *reinterpret_cast<unsigned*>(&hh);
    l = *reinterpret_cast<unsigned*>(&ll);
}
// m16n8k16 f16 MMA, fp32 accumulate
__device__ __forceinline__ void mma_f16(float* c, const unsigned* a, const unsigned* b) {
    asm volatile(
        "mma.sync.aligned.m16n8k16.row.col.f32.f16.f16.f32 "
        "{%0,%1,%2,%3}, {%4,%5,%6,%7}, {%8,%9}, {%0,%1,%2,%3};\n"
        : "+f"(c[0]), "+f"(c[1]), "+f"(c[2]), "+f"(c[3])
        : "r"(a[0]), "r"(a[1]), "r"(a[2]), "r"(a[3]), "r"(b[0]), "r"(b[1]));
}

// ---------------------------------------------------------------------------
// Tensor-core projection GEMM, split-FP16 (hi*hi + hi*lo + lo*hi).
// Unchanged from R14 (passing, ~360us for the pair).
// ---------------------------------------------------------------------------
template <int K, int KT, int SRC>
__global__ __launch_bounds__(256) void gemm_f16(
    const float* __restrict__ Ain, const float* __restrict__ W,
    const float* __restrict__ b1, const float* __restrict__ b2)
{
    const float* __restrict__ A = (SRC == 0) ? Ain : (const float*)g_h1;

    __shared__ unsigned AsH[128][12], AsL[128][12];
    __shared__ unsigned BsH[40][12],  BsL[40][12];

    const int tid  = threadIdx.x;
    const int lane = tid & 31;
    const int warp = tid >> 5;
    const int wm   = warp * 16;
    const int g    = lane >> 2;
    const int tg   = lane & 3;
    const int m0   = blockIdx.x * 128;
    const int n0   = blockIdx.y * 40;

    const int arow = tid >> 1;
    const int akq  = tid & 1;
    const int brow = tid >> 2;
    const int bkj  = tid & 3;

    float acc[5][4];
    #pragma unroll
    for (int nf = 0; nf < 5; ++nf)
        #pragma unroll
        for (int i = 0; i < 4; ++i) acc[nf][i] = 0.f;

    float va[8];
    float vb[4];

    {
        #pragma unroll
        for (int j = 0; j < 8; ++j) {
            int k = akq * 8 + j;
            va[j] = (k < K) ? A[(size_t)(m0 + arow) * K + k] : 0.f;
        }
        if (brow < 40) {
            #pragma unroll
            for (int j = 0; j < 4; ++j) {
                int k = bkj * 4 + j;
                vb[j] = (k < K) ? W[(size_t)(n0 + brow) * K + k] : 0.f;
            }
        }
    }

    for (int kt = 0; kt < KT; ++kt) {
        __syncthreads();
        #pragma unroll
        for (int p = 0; p < 4; ++p) {
            unsigned h, l;
            split16(va[2 * p], va[2 * p + 1], h, l);
            AsH[arow][akq * 4 + p] = h;
            AsL[arow][akq * 4 + p] = l;
        }
        if (brow < 40) {
            #pragma unroll
            for (int p = 0; p < 2; ++p) {
                unsigned h, l;
                split16(vb[2 * p], vb[2 * p + 1], h, l);
                BsH[brow][bkj * 2 + p] = h;
                BsL[brow][bkj * 2 + p] = l;
            }
        }
        __syncthreads();

        if (kt + 1 < KT) {
            const int k0 = (kt + 1) * 16;
            #pragma unroll
            for (int j = 0; j < 8; ++j) {
                int k = k0 + akq * 8 + j;
                va[j] = (k < K) ? A[(size_t)(m0 + arow) * K + k] : 0.f;
            }
            if (brow < 40) {
                #pragma unroll
                for (int j = 0; j < 4; ++j) {
                    int k = k0 + bkj * 4 + j;
                    vb[j] = (k < K) ? W[(size_t)(n0 + brow) * K + k] : 0.f;
                }
            }
        }

        {
            unsigned aH[4], aL[4];
            aH[0] = AsH[wm + g][tg];      aH[1] = AsH[wm + g + 8][tg];
            aH[2] = AsH[wm + g][tg + 4];  aH[3] = AsH[wm + g + 8][tg + 4];
            aL[0] = AsL[wm + g][tg];      aL[1] = AsL[wm + g + 8][tg];
            aL[2] = AsL[wm + g][tg + 4];  aL[3] = AsL[wm + g + 8][tg + 4];
            #pragma unroll
            for (int nf = 0; nf < 5; ++nf) {
                unsigned bH[2], bL[2];
                bH[0] = BsH[nf * 8 + g][tg]; bH[1] = BsH[nf * 8 + g][tg + 4];
                bL[0] = BsL[nf * 8 + g][tg]; bL[1] = BsL[nf * 8 + g][tg + 4];
                mma_f16(acc[nf], aH, bH);
                mma_f16(acc[nf], aH, bL);
                mma_f16(acc[nf], aL, bH);
            }
        }
    }

    const int m_lo = m0 + wm + g;
    const int m_hi = m_lo + 8;
    #pragma unroll
    for (int nf = 0; nf < 5; ++nf) {
        const int n = n0 + nf * 8 + 2 * tg;
        float bs0 = __ldg(&b1[n])     + __ldg(&b2[n]);
        float bs1 = __ldg(&b1[n + 1]) + __ldg(&b2[n + 1]);
        g_xproj[(size_t)m_lo * GG + n]     = acc[nf][0] + bs0;
        g_xproj[(size_t)m_lo * GG + n + 1] = acc[nf][1] + bs1;
        g_xproj[(size_t)m_hi * GG + n]     = acc[nf][2] + bs0;
        g_xproj[(size_t)m_hi * GG + n + 1] = acc[nf][3] + bs1;
    }
}

// ---------------------------------------------------------------------------
// LSTM recurrence v4 — halve the LDS-broadcast wavefront pressure.
//   - One block = one batch = 128 threads (grid 512, occ 4 -> single wave).
//   - Thread 2u+a handles TWO gate rows of unit u: gates (2a, 2a+1).
//     The 13 h-broadcast LDS.128 per step now feed 100 MACs (was 50):
//     per-SM wavefronts/step drop ~2x vs rec3 (the measured L1=63% wall).
//   - a=0 holds (i,f), a=1 holds (g,o) -> cell update via 2 shfl_down.
//   - h double-buffered in shared; ONE __syncthreads per step.
//   - branch-free activation select; distance-2 x-projection prefetch.
// ---------------------------------------------------------------------------
template <int WRITE_ALL>
__global__ __launch_bounds__(128, 4) void lstm_rec4(
    const float* __restrict__ w_hh)  // [G, H]
{
    __shared__ float hbuf[2][64];     // [buf][unit]; pads stay 0

    const int j = threadIdx.x;        // 0..127
    const int u = j >> 1;             // 0..63
    const int a = j & 1;              // 0: rows i,f   1: rows g,o
    const bool real = (u < HH);
    const int b = blockIdx.x;
    const int r0 = (2 * a) * HH + u;  // first gate row
    const int r1 = r0 + HH;           // second gate row

    // Two w_hh rows in registers as packed f32x2 (25 pairs + zero pad pair)
    unsigned long long w0[26], w1[26];
    if (real) {
        #pragma unroll
        for (int k = 0; k < 25; ++k) {
            w0[k] = pk2(__ldg(&w_hh[r0 * HH + 2 * k]), __ldg(&w_hh[r0 * HH + 2 * k + 1]));
            w1[k] = pk2(__ldg(&w_hh[r1 * HH + 2 * k]), __ldg(&w_hh[r1 * HH + 2 * k + 1]));
        }
    } else {
        #pragma unroll
        for (int k = 0; k < 25; ++k) { w0[k] = 0ull; w1[k] = 0ull; }
    }
    w0[25] = 0ull; w1[25] = 0ull;

    ((float*)hbuf)[j] = 0.f;          // zero both 64-float buffers

    float c = 0.f;
    const float* xp0 = g_xproj + (size_t)b * TT * GG + (real ? r0 : 0);
    const float* xp1 = xp0 + (real ? HH : 0);
    float x0a = real ? __ldg(xp0)      : 0.f;
    float x1a = real ? __ldg(xp1)      : 0.f;
    float x0b = real ? __ldg(xp0 + GG) : 0.f;
    float x1b = real ? __ldg(xp1 + GG) : 0.f;

    __syncthreads();

    for (int t = 0; t < TT; ++t) {
        const int buf = t & 1;
        // prefetch t+2
        float x0n = 0.f, x1n = 0.f;
        if (real && t + 2 < TT) {
            x0n = __ldg(xp0 + (size_t)(t + 2) * GG);
            x1n = __ldg(xp1 + (size_t)(t + 2) * GG);
        }

        // two dot products sharing the same broadcast h loads
        const ulonglong2* h2 = (const ulonglong2*)hbuf[buf];
        unsigned long long p00 = 0ull, p01 = 0ull, p10 = 0ull, p11 = 0ull;
        #pragma unroll
        for (int kk = 0; kk < 13; ++kk) {
            ulonglong2 hv = h2[kk];
            p00 = fma2(w0[2 * kk],     hv.x, p00);
            p01 = fma2(w0[2 * kk + 1], hv.y, p01);
            p10 = fma2(w1[2 * kk],     hv.x, p10);
            p11 = fma2(w1[2 * kk + 1], hv.y, p11);
        }
        float2 s00 = upk2(p00), s01 = upk2(p01);
        float2 s10 = upk2(p10), s11 = upk2(p11);
        float pre0 = x0a + ((s00.x + s00.y) + (s01.x + s01.y));
        float pre1 = x1a + ((s10.x + s10.y) + (s11.x + s11.y));

        // activations: gate(2a) -> a=0: i(sig), a=1: g(tanh); gate(2a+1) -> f/o: sig
        float arg = a ? pre0 : 0.5f * pre0;
        float th  = fast_tanh(arg);
        float v0  = a ? th : fmaf(0.5f, th, 0.5f);
        float v1  = fast_sigmoid(pre1);

        // a=0 fetches (g, o) from its odd neighbor
        float gv = __shfl_down_sync(0xffffffffu, v0, 1);
        float ov = __shfl_down_sync(0xffffffffu, v1, 1);

        if (a == 0) {
            c = fmaf(v1, c, v0 * gv);          // v0=i, v1=f
            float h = ov * fast_tanh(c);
            hbuf[buf ^ 1][u] = real ? h : 0.f;
            if (WRITE_ALL) {
                if (real) g_h1[((size_t)b * TT + t) * HH + u] = h;
            } else {
                if (real && t == TT - 1) g_hlast[(size_t)b * HH + u] = h;
            }
        }

        x0a = x0b; x0b = x0n;
        x1a = x1b; x1b = x1n;
        __syncthreads();
    }
}

// ---------------------------------------------------------------------------
// Final FC: out[b][o] = sum_k g_hlast[b][k] * w_fc[o][k] + b_fc[o]
// ---------------------------------------------------------------------------
__global__ __launch_bounds__(OO) void fc_kernel(
    const float* __restrict__ w_fc, const float* __restrict__ b_fc,
    float* __restrict__ out)
{
    __shared__ float hs[HH];
    const int b = blockIdx.x;
    const int o = threadIdx.x;
    if (o < HH) hs[o] = g_hlast[b * HH + o];
    __syncthreads();
    float acc = b_fc[o];
    #pragma unroll
    for (int k = 0; k < HH; ++k) acc = fmaf(__ldg(&w_fc[o * HH + k]), hs[k], acc);
    out[(size_t)b * OO + o] = acc;
}

// ---------------------------------------------------------------------------
extern "C" void kernel_launch(void* const* d_in, const int* in_sizes, int n_in,
                              void* d_out, int out_size)
{
    (void)in_sizes; (void)n_in; (void)out_size;
    const float* x     = (const float*)d_in[0];
    const float* w_ih0 = (const float*)d_in[1];
    const float* w_hh0 = (const float*)d_in[2];
    const float* b_ih0 = (const float*)d_in[3];
    const float* b_hh0 = (const float*)d_in[4];
    const float* w_ih1 = (const float*)d_in[5];
    const float* w_hh1 = (const float*)d_in[6];
    const float* b_ih1 = (const float*)d_in[7];
    const float* b_hh1 = (const float*)d_in[8];
    const float* w_fc  = (const float*)d_in[9];
    const float* b_fc  = (const float*)d_in[10];
    float* out = (float*)d_out;

    dim3 gemmGrid(MM / 128, 5);   // 1024 x 5, N covered exactly

    gemm_f16<II, 9, 0><<<gemmGrid, 256>>>(x, w_ih0, b_ih0, b_hh0);
    lstm_rec4<1><<<BB, 128>>>(w_hh0);
    gemm_f16<HH, 4, 1><<<gemmGrid, 256>>>(nullptr, w_ih1, b_ih1, b_hh1);
    lstm_rec4<0><<<BB, 128>>>(w_hh1);
    fc_kernel<<<BB, OO>>>(w_fc, b_fc, out);
}

// round 16
// speedup vs baseline: 2.0135x; 1.1506x over previous
#include <cuda_runtime.h>
#include <cuda_fp16.h>
#include <math.h>

// Problem constants
#define BB   512          // batch
#define TT   256          // time steps
#define HH   50           // hidden
#define GG   200          // 4*H gates
#define II   144          // input features
#define MM   (BB*TT)      // 131072 rows for the projection GEMMs
#define OO   144          // fc output
#define HP   64           // padded hidden (fp16 image row stride for layer-1 A/W)

// Scratch (static __device__ globals — no allocations anywhere).
__device__ float g_xproj[(size_t)MM * GG];                 // ~105 MB, both layers
__device__ float g_hlast[BB * HH];                         // layer-1 final hidden
// fp16 hi/lo images (16B-aligned for vector access)
__device__ __align__(16) __half g_xh[(size_t)MM * II];     // x hi   (37.7 MB)
__device__ __align__(16) __half g_xl[(size_t)MM * II];     // x lo
__device__ __align__(16) __half g_h1h[(size_t)MM * HP];    // h1 hi  (16.8 MB, padded)
__device__ __align__(16) __half g_h1l[(size_t)MM * HP];    // h1 lo
__device__ __align__(16) __half g_w0h[GG * II], g_w0l[GG * II];
__device__ __align__(16) __half g_w1h[GG * HP], g_w1l[GG * HP];  // padded cols 50..63 = 0

// ---------------------------------------------------------------------------
// Small helpers
// ---------------------------------------------------------------------------
__device__ __forceinline__ float fast_tanh(float x) {
    float y; asm("tanh.approx.f32 %0, %1;" : "=f"(y) : "f"(x)); return y;
}
__device__ __forceinline__ float fast_sigmoid(float x) {
    return fmaf(0.5f, fast_tanh(0.5f * x), 0.5f);
}
__device__ __forceinline__ unsigned long long pk2(float lo, float hi) {
    unsigned long long r; asm("mov.b64 %0, {%1, %2};" : "=l"(r) : "f"(lo), "f"(hi)); return r;
}
__device__ __forceinline__ float2 upk2(unsigned long long v) {
    float2 f; asm("mov.b64 {%0, %1}, %2;" : "=f"(f.x), "=f"(f.y) : "l"(v)); return f;
}
__device__ __forceinline__ unsigned long long fma2(
    unsigned long long a, unsigned long long b, unsigned long long c) {
    unsigned long long d;
    asm("fma.rn.f32x2 %0, %1, %2, %3;" : "=l"(d) : "l"(a), "l"(b), "l"(c));
    return d;
}
// m16n8k16 f16 MMA, fp32 accumulate
__device__ __forceinline__ void mma_f16(float* c, const unsigned* a, const unsigned* b) {
    asm volatile(
        "mma.sync.aligned.m16n8k16.row.col.f32.f16.f16.f32 "
        "{%0,%1,%2,%3}, {%4,%5,%6,%7}, {%8,%9}, {%0,%1,%2,%3};\n"
        : "+f"(c[0]), "+f"(c[1]), "+f"(c[2]), "+f"(c[3])
        : "r"(a[0]), "r"(a[1]), "r"(a[2]), "r"(a[3]), "r"(b[0]), "r"(b[1]));
}

// ---------------------------------------------------------------------------
// Pre-pass 1: convert x (fp32, [MM*II] contiguous) -> fp16 hi/lo images.
// Pure streaming: 8 elems per thread.
// ---------------------------------------------------------------------------
__global__ __launch_bounds__(256) void conv_x(const float* __restrict__ x)
{
    size_t gbase = ((size_t)blockIdx.x * 256 + threadIdx.x) * 8;
    float4 p0 = *(const float4*)&x[gbase];
    float4 p1 = *(const float4*)&x[gbase + 4];
    float v[8] = {p0.x, p0.y, p0.z, p0.w, p1.x, p1.y, p1.z, p1.w};
    __half hs[8], ls[8];
    #pragma unroll
    for (int i = 0; i < 8; ++i) {
        hs[i] = __float2half_rn(v[i]);
        ls[i] = __float2half_rn(v[i] - __half2float(hs[i]));
    }
    *(uint4*)&g_xh[gbase] = *(uint4*)hs;
    *(uint4*)&g_xl[gbase] = *(uint4*)ls;
}

// ---------------------------------------------------------------------------
// Pre-pass 2: convert both weight matrices (tiny). One block per gate row.
// W1 image padded to HP columns with zeros.
// ---------------------------------------------------------------------------
__global__ __launch_bounds__(256) void conv_w(
    const float* __restrict__ w0, const float* __restrict__ w1)
{
    const int r = blockIdx.x;      // 0..199
    const int t = threadIdx.x;
    if (t < II) {
        float v = w0[r * II + t];
        __half h = __float2half_rn(v);
        g_w0h[r * II + t] = h;
        g_w0l[r * II + t] = __float2half_rn(v - __half2float(h));
    }
    if (t < HP) {
        float v = (t < HH) ? w1[r * HH + t] : 0.f;
        __half h = __float2half_rn(v);
        g_w1h[r * HP + t] = h;
        g_w1l[r * HP + t] = __float2half_rn(v - __half2float(h));
    }
}

// ---------------------------------------------------------------------------
// Tensor-core projection GEMM over pre-split fp16 images.
//   g_xproj[m][n] = sum_k A[m][k]*W[n][k] + b1[n] + b2[n]   (3-term split)
// Block tile 128(M) x 40(N), 256 threads = 8 warps, warp = 16 rows x 40 cols.
// Staging is now a pure vector copy: A = 2 LDG.128 + 2 STS.128 per thread
// per stage; B = 2 LDG.64 + 2 STS.64. No conversion in the hot loop.
// SRC=0: A image = g_xh/g_xl (stride II), W = g_w0*.
// SRC=1: A image = g_h1h/g_h1l (stride HP), W = g_w1*.
// ---------------------------------------------------------------------------
template <int KA, int KT, int SRC>
__global__ __launch_bounds__(256) void gemm_img(
    const float* __restrict__ b1, const float* __restrict__ b2)
{
    const __half* __restrict__ Ah = (SRC == 0) ? g_xh : g_h1h;
    const __half* __restrict__ Al = (SRC == 0) ? g_xl : g_h1l;
    const __half* __restrict__ Wh = (SRC == 0) ? g_w0h : g_w1h;
    const __half* __restrict__ Wl = (SRC == 0) ? g_w0l : g_w1l;

    // k-pairs as u32: 8 used per row, stride 12 u32 (48B)
    __shared__ unsigned AsH[128][12], AsL[128][12];
    __shared__ unsigned BsH[40][12],  BsL[40][12];

    const int tid  = threadIdx.x;
    const int lane = tid & 31;
    const int warp = tid >> 5;
    const int wm   = warp * 16;
    const int g    = lane >> 2;
    const int tg   = lane & 3;
    const int m0   = blockIdx.x * 128;
    const int n0   = blockIdx.y * 40;

    const int arow = tid >> 1;         // 0..127
    const int akq  = tid & 1;          // 8-half chunk (16B)
    const int brow = tid >> 2;         // 0..63 (valid < 40)
    const int bkj  = tid & 3;          // 4-half chunk (8B)

    float acc[5][4];
    #pragma unroll
    for (int nf = 0; nf < 5; ++nf)
        #pragma unroll
        for (int i = 0; i < 4; ++i) acc[nf][i] = 0.f;

    const size_t abase = (size_t)(m0 + arow) * KA + akq * 8;
    const size_t bbase = (size_t)(n0 + brow) * KA + bkj * 4;   // W stride == KA

    uint4 vah, val;      // A stage regs (8 halves each)
    uint2 vbh, vbl;      // B stage regs (4 halves each)

    vah = *(const uint4*)(Ah + abase);
    val = *(const uint4*)(Al + abase);
    if (brow < 40) {
        vbh = *(const uint2*)(Wh + bbase);
        vbl = *(const uint2*)(Wl + bbase);
    }

    for (int kt = 0; kt < KT; ++kt) {
        __syncthreads();
        *(uint4*)&AsH[arow][akq * 4] = vah;
        *(uint4*)&AsL[arow][akq * 4] = val;
        if (brow < 40) {
            *(uint2*)&BsH[brow][bkj * 2] = vbh;
            *(uint2*)&BsL[brow][bkj * 2] = vbl;
        }
        __syncthreads();

        if (kt + 1 < KT) {
            const size_t ao = abase + (size_t)(kt + 1) * 16;
            vah = *(const uint4*)(Ah + ao);
            val = *(const uint4*)(Al + ao);
            if (brow < 40) {
                const size_t bo = bbase + (size_t)(kt + 1) * 16;
                vbh = *(const uint2*)(Wh + bo);
                vbl = *(const uint2*)(Wl + bo);
            }
        }

        {
            unsigned aH[4], aL[4];
            aH[0] = AsH[wm + g][tg];      aH[1] = AsH[wm + g + 8][tg];
            aH[2] = AsH[wm + g][tg + 4];  aH[3] = AsH[wm + g + 8][tg + 4];
            aL[0] = AsL[wm + g][tg];      aL[1] = AsL[wm + g + 8][tg];
            aL[2] = AsL[wm + g][tg + 4];  aL[3] = AsL[wm + g + 8][tg + 4];
            #pragma unroll
            for (int nf = 0; nf < 5; ++nf) {
                unsigned bH[2], bL[2];
                bH[0] = BsH[nf * 8 + g][tg]; bH[1] = BsH[nf * 8 + g][tg + 4];
                bL[0] = BsL[nf * 8 + g][tg]; bL[1] = BsL[nf * 8 + g][tg + 4];
                mma_f16(acc[nf], aH, bH);
                mma_f16(acc[nf], aH, bL);
                mma_f16(acc[nf], aL, bH);
            }
        }
    }

    const int m_lo = m0 + wm + g;
    const int m_hi = m_lo + 8;
    #pragma unroll
    for (int nf = 0; nf < 5; ++nf) {
        const int n = n0 + nf * 8 + 2 * tg;
        float bs0 = __ldg(&b1[n])     + __ldg(&b2[n]);
        float bs1 = __ldg(&b1[n + 1]) + __ldg(&b2[n + 1]);
        g_xproj[(size_t)m_lo * GG + n]     = acc[nf][0] + bs0;
        g_xproj[(size_t)m_lo * GG + n + 1] = acc[nf][1] + bs1;
        g_xproj[(size_t)m_hi * GG + n]     = acc[nf][2] + bs0;
        g_xproj[(size_t)m_hi * GG + n + 1] = acc[nf][3] + bs1;
    }
}

// ---------------------------------------------------------------------------
// LSTM recurrence v4 (structure unchanged from R15; layer-0 variant now emits
// h directly as fp16 hi/lo into the padded g_h1h/g_h1l images — layer-1's A
// conversion is free).
// ---------------------------------------------------------------------------
template <int WRITE_ALL>
__global__ __launch_bounds__(128, 4) void lstm_rec4(
    const float* __restrict__ w_hh)  // [G, H]
{
    __shared__ float hbuf[2][64];

    const int j = threadIdx.x;        // 0..127
    const int u = j >> 1;             // 0..63
    const int a = j & 1;              // 0: rows i,f   1: rows g,o
    const bool real = (u < HH);
    const int b = blockIdx.x;
    const int r0 = (2 * a) * HH + u;
    const int r1 = r0 + HH;

    unsigned long long w0[26], w1[26];
    if (real) {
        #pragma unroll
        for (int k = 0; k < 25; ++k) {
            w0[k] = pk2(__ldg(&w_hh[r0 * HH + 2 * k]), __ldg(&w_hh[r0 * HH + 2 * k + 1]));
            w1[k] = pk2(__ldg(&w_hh[r1 * HH + 2 * k]), __ldg(&w_hh[r1 * HH + 2 * k + 1]));
        }
    } else {
        #pragma unroll
        for (int k = 0; k < 25; ++k) { w0[k] = 0ull; w1[k] = 0ull; }
    }
    w0[25] = 0ull; w1[25] = 0ull;

    ((float*)hbuf)[j] = 0.f;

    float c = 0.f;
    const float* xp0 = g_xproj + (size_t)b * TT * GG + (real ? r0 : 0);
    const float* xp1 = xp0 + (real ? HH : 0);
    float x0a = real ? __ldg(xp0)      : 0.f;
    float x1a = real ? __ldg(xp1)      : 0.f;
    float x0b = real ? __ldg(xp0 + GG) : 0.f;
    float x1b = real ? __ldg(xp1 + GG) : 0.f;

    __syncthreads();

    for (int t = 0; t < TT; ++t) {
        const int buf = t & 1;
        float x0n = 0.f, x1n = 0.f;
        if (real && t + 2 < TT) {
            x0n = __ldg(xp0 + (size_t)(t + 2) * GG);
            x1n = __ldg(xp1 + (size_t)(t + 2) * GG);
        }

        const ulonglong2* h2 = (const ulonglong2*)hbuf[buf];
        unsigned long long p00 = 0ull, p01 = 0ull, p10 = 0ull, p11 = 0ull;
        #pragma unroll
        for (int kk = 0; kk < 13; ++kk) {
            ulonglong2 hv = h2[kk];
            p00 = fma2(w0[2 * kk],     hv.x, p00);
            p01 = fma2(w0[2 * kk + 1], hv.y, p01);
            p10 = fma2(w1[2 * kk],     hv.x, p10);
            p11 = fma2(w1[2 * kk + 1], hv.y, p11);
        }
        float2 s00 = upk2(p00), s01 = upk2(p01);
        float2 s10 = upk2(p10), s11 = upk2(p11);
        float pre0 = x0a + ((s00.x + s00.y) + (s01.x + s01.y));
        float pre1 = x1a + ((s10.x + s10.y) + (s11.x + s11.y));

        float arg = a ? pre0 : 0.5f * pre0;
        float th  = fast_tanh(arg);
        float v0  = a ? th : fmaf(0.5f, th, 0.5f);
        float v1  = fast_sigmoid(pre1);

        float gv = __shfl_down_sync(0xffffffffu, v0, 1);
        float ov = __shfl_down_sync(0xffffffffu, v1, 1);

        if (a == 0) {
            c = fmaf(v1, c, v0 * gv);
            float h = ov * fast_tanh(c);
            float hw = real ? h : 0.f;
            hbuf[buf ^ 1][u] = hw;
            if (WRITE_ALL) {
                // emit fp16 hi/lo image, padded cols (u>=50) get zeros
                __half hh = __float2half_rn(hw);
                __half hl = __float2half_rn(hw - __half2float(hh));
                size_t idx = ((size_t)b * TT + t) * HP + u;
                g_h1h[idx] = hh;
                g_h1l[idx] = hl;
            } else {
                if (real && t == TT - 1) g_hlast[(size_t)b * HH + u] = h;
            }
        }

        x0a = x0b; x0b = x0n;
        x1a = x1b; x1b = x1n;
        __syncthreads();
    }
}

// ---------------------------------------------------------------------------
// Final FC: out[b][o] = sum_k g_hlast[b][k] * w_fc[o][k] + b_fc[o]
// ---------------------------------------------------------------------------
__global__ __launch_bounds__(OO) void fc_kernel(
    const float* __restrict__ w_fc, const float* __restrict__ b_fc,
    float* __restrict__ out)
{
    __shared__ float hs[HH];
    const int b = blockIdx.x;
    const int o = threadIdx.x;
    if (o < HH) hs[o] = g_hlast[b * HH + o];
    __syncthreads();
    float acc = b_fc[o];
    #pragma unroll
    for (int k = 0; k < HH; ++k) acc = fmaf(__ldg(&w_fc[o * HH + k]), hs[k], acc);
    out[(size_t)b * OO + o] = acc;
}

// ---------------------------------------------------------------------------
extern "C" void kernel_launch(void* const* d_in, const int* in_sizes, int n_in,
                              void* d_out, int out_size)
{
    (void)in_sizes; (void)n_in; (void)out_size;
    const float* x     = (const float*)d_in[0];
    const float* w_ih0 = (const float*)d_in[1];
    const float* w_hh0 = (const float*)d_in[2];
    const float* b_ih0 = (const float*)d_in[3];
    const float* b_hh0 = (const float*)d_in[4];
    const float* w_ih1 = (const float*)d_in[5];
    const float* w_hh1 = (const float*)d_in[6];
    const float* b_ih1 = (const float*)d_in[7];
    const float* b_hh1 = (const float*)d_in[8];
    const float* w_fc  = (const float*)d_in[9];
    const float* b_fc  = (const float*)d_in[10];
    float* out = (float*)d_out;

    dim3 gemmGrid(MM / 128, 5);   // 1024 x 5

    conv_x<<<(MM * II) / (256 * 8), 256>>>(x);              // 9216 blocks
    conv_w<<<GG, 256>>>(w_ih0, w_ih1);
    gemm_img<II, 9, 0><<<gemmGrid, 256>>>(b_ih0, b_hh0);
    lstm_rec4<1><<<BB, 128>>>(w_hh0);
    gemm_img<HP, 4, 1><<<gemmGrid, 256>>>(b_ih1, b_hh1);
    lstm_rec4<0><<<BB, 128>>>(w_hh1);
    fc_kernel<<<BB, OO>>>(w_fc, b_fc, out);
}